// round 12
// baseline (speedup 1.0000x reference)
#include <cuda_runtime.h>
#include <math.h>
#include <stdint.h>

// ---------------------------------------------------------------------------
// Problem constants
// ---------------------------------------------------------------------------
#define BATCH 32
#define GD    512
#define LD    256
#define DIM   384
#define TH    3
#define THD   32
#define HOUT  4
#define DH    96
#define HID   128
#define ROWS  (BATCH * 512)   // 16384

// ---------------------------------------------------------------------------
// Scratch (both streams batched: [0]=global, [1]=local)
// ---------------------------------------------------------------------------
__device__ float g_act[2 * ROWS * DIM];
__device__ float g_qkv[2 * ROWS * 288];
__device__ float g_attnout[2 * ROWS * 96];
__device__ float g_ff[2 * ROWS * 128];
__device__ float g_qh[ROWS * DIM];
__device__ float g_kh[ROWS * DIM];
__device__ float g_lpart[128 * 4 * 384];
__device__ float g_lnstat[2 * ROWS * 2];
__device__ int   g_mask[ROWS];

// ---------------------------------------------------------------------------
// TF32 helpers
// ---------------------------------------------------------------------------
__device__ __forceinline__ float to_tf32(float x) {
    uint32_t u;
    asm("cvt.rna.tf32.f32 %0, %1;" : "=r"(u) : "f"(x));
    return __uint_as_float(u);
}

__device__ __forceinline__ void mma_tf32(float* d, const uint32_t* a, const uint32_t* b) {
    asm volatile(
        "mma.sync.aligned.m16n8k8.row.col.f32.tf32.tf32.f32 "
        "{%0,%1,%2,%3}, {%4,%5,%6,%7}, {%8,%9}, {%0,%1,%2,%3};"
        : "+f"(d[0]), "+f"(d[1]), "+f"(d[2]), "+f"(d[3])
        : "r"(a[0]), "r"(a[1]), "r"(a[2]), "r"(a[3]), "r"(b[0]), "r"(b[1]));
}

// ---------------------------------------------------------------------------
// Row LN stats: stat[row] = {mean, rstd}. One warp per row.
// ---------------------------------------------------------------------------
__global__ void lnstats_k(const float* __restrict__ x, float* __restrict__ stat)
{
    int row = blockIdx.x * 8 + (threadIdx.x >> 5);
    int lane = threadIdx.x & 31;
    const float* xr = x + (long long)row * DIM;
    float s = 0.f, s2 = 0.f;
    #pragma unroll
    for (int i = 0; i < 12; i++) {
        float v = xr[lane + 32 * i];
        s += v; s2 += v * v;
    }
    #pragma unroll
    for (int o = 16; o > 0; o >>= 1) {
        s  += __shfl_xor_sync(0xffffffffu, s, o);
        s2 += __shfl_xor_sync(0xffffffffu, s2, o);
    }
    if (lane == 0) {
        float mean = s * (1.f / DIM);
        float var = s2 * (1.f / DIM) - mean * mean;
        stat[row * 2] = mean;
        stat[row * 2 + 1] = rsqrtf(var + 1e-5f);
    }
}

// ---------------------------------------------------------------------------
// TF32 GEMM, 256 thr, double-buffered, scalar frag loads (conflict-free).
// C = act((LNA ? LN(A) : A) @ W + bias) (+ residual)
// Batched via blockIdx.z: A += z*sA, C += z*sC, res += z*sC,
//   W += (z/wdiv)*sW, lnstat += z*sLn.
// ---------------------------------------------------------------------------
template<int ACT, bool RES, bool LNA>
__global__ __launch_bounds__(256, 2)
void gemm_tc(const float* __restrict__ A, const float* __restrict__ W,
             const float* __restrict__ bias, const float* __restrict__ res,
             float* __restrict__ C,
             const float* __restrict__ lnstat, const float* __restrict__ lng,
             const float* __restrict__ lnb,
             int M, int N, int K,
             long long sA, long long sW, long long sC, long long sLn, int wdiv)
{
    int z = blockIdx.z;
    A += (long long)z * sA;
    C += (long long)z * sC;
    W += (long long)(z / wdiv) * sW;
    if (LNA) lnstat += (long long)z * sLn;
    const float* Rp = RES ? (res + (long long)z * sC) : nullptr;

    __shared__ __align__(16) float As[2][128][20];
    __shared__ __align__(16) float Bs[2][16][136];

    int m0 = blockIdx.y * 128, n0 = blockIdx.x * 128;
    int tid = threadIdx.x;
    int warp = tid >> 5, lane = tid & 31;
    int wm = (warp >> 2) * 64;
    int wn = (warp & 3) * 32;

    float acc[4][4][4];
    #pragma unroll
    for (int i = 0; i < 4; i++)
        #pragma unroll
        for (int j = 0; j < 4; j++)
            #pragma unroll
            for (int r = 0; r < 4; r++) acc[i][j][r] = 0.f;

    int arow = tid >> 1, akq = (tid & 1) * 8;
    const float* Ap = A + (long long)(m0 + arow) * K + akq;
    int bkr = tid >> 4, bnq = (tid & 15) * 8;
    const float* Wp = W + (long long)bkr * N + n0 + bnq;
    bool nok = (n0 + bnq < N);

    float mean = 0.f, rstd = 0.f;
    if (LNA) {
        mean = lnstat[(m0 + arow) * 2];
        rstd = lnstat[(m0 + arow) * 2 + 1];
    }

    float4 av0 = *(const float4*)Ap;
    float4 av1 = *(const float4*)(Ap + 4);
    float4 bv0 = nok ? *(const float4*)Wp       : make_float4(0, 0, 0, 0);
    float4 bv1 = nok ? *(const float4*)(Wp + 4) : make_float4(0, 0, 0, 0);

    int KT = K >> 4;
    for (int kt = 0; kt < KT; kt++) {
        int buf = kt & 1;
        if (LNA) {
            int kg = kt * 16 + akq;
            float4 g0 = *(const float4*)&lng[kg];
            float4 g1 = *(const float4*)&lng[kg + 4];
            float4 b0 = *(const float4*)&lnb[kg];
            float4 b1 = *(const float4*)&lnb[kg + 4];
            As[buf][arow][akq + 0] = to_tf32((av0.x - mean) * rstd * g0.x + b0.x);
            As[buf][arow][akq + 1] = to_tf32((av0.y - mean) * rstd * g0.y + b0.y);
            As[buf][arow][akq + 2] = to_tf32((av0.z - mean) * rstd * g0.z + b0.z);
            As[buf][arow][akq + 3] = to_tf32((av0.w - mean) * rstd * g0.w + b0.w);
            As[buf][arow][akq + 4] = to_tf32((av1.x - mean) * rstd * g1.x + b1.x);
            As[buf][arow][akq + 5] = to_tf32((av1.y - mean) * rstd * g1.y + b1.y);
            As[buf][arow][akq + 6] = to_tf32((av1.z - mean) * rstd * g1.z + b1.z);
            As[buf][arow][akq + 7] = to_tf32((av1.w - mean) * rstd * g1.w + b1.w);
        } else {
            As[buf][arow][akq + 0] = to_tf32(av0.x);
            As[buf][arow][akq + 1] = to_tf32(av0.y);
            As[buf][arow][akq + 2] = to_tf32(av0.z);
            As[buf][arow][akq + 3] = to_tf32(av0.w);
            As[buf][arow][akq + 4] = to_tf32(av1.x);
            As[buf][arow][akq + 5] = to_tf32(av1.y);
            As[buf][arow][akq + 6] = to_tf32(av1.z);
            As[buf][arow][akq + 7] = to_tf32(av1.w);
        }
        Bs[buf][bkr][bnq + 0] = to_tf32(bv0.x);
        Bs[buf][bkr][bnq + 1] = to_tf32(bv0.y);
        Bs[buf][bkr][bnq + 2] = to_tf32(bv0.z);
        Bs[buf][bkr][bnq + 3] = to_tf32(bv0.w);
        Bs[buf][bkr][bnq + 4] = to_tf32(bv1.x);
        Bs[buf][bkr][bnq + 5] = to_tf32(bv1.y);
        Bs[buf][bkr][bnq + 6] = to_tf32(bv1.z);
        Bs[buf][bkr][bnq + 7] = to_tf32(bv1.w);

        if (kt + 1 < KT) {
            Ap += 16;
            Wp += (long long)16 * N;
            av0 = *(const float4*)Ap;
            av1 = *(const float4*)(Ap + 4);
            if (nok) {
                bv0 = *(const float4*)Wp;
                bv1 = *(const float4*)(Wp + 4);
            }
        }

        __syncthreads();

        #pragma unroll
        for (int ks = 0; ks < 2; ks++) {
            int ko = ks * 8;
            uint32_t af[4][4], bf[4][2];
            #pragma unroll
            for (int i = 0; i < 4; i++) {
                int mr = wm + i * 16 + (lane >> 2);
                int kc = ko + (lane & 3);
                af[i][0] = __float_as_uint(As[buf][mr][kc]);
                af[i][1] = __float_as_uint(As[buf][mr + 8][kc]);
                af[i][2] = __float_as_uint(As[buf][mr][kc + 4]);
                af[i][3] = __float_as_uint(As[buf][mr + 8][kc + 4]);
            }
            #pragma unroll
            for (int j = 0; j < 4; j++) {
                int nc = wn + j * 8 + (lane >> 2);
                int kr = ko + (lane & 3);
                bf[j][0] = __float_as_uint(Bs[buf][kr][nc]);
                bf[j][1] = __float_as_uint(Bs[buf][kr + 4][nc]);
            }
            #pragma unroll
            for (int i = 0; i < 4; i++)
                #pragma unroll
                for (int j = 0; j < 4; j++)
                    mma_tf32(acc[i][j], af[i], bf[j]);
        }
    }

    #pragma unroll
    for (int i = 0; i < 4; i++) {
        long long r0 = m0 + wm + i * 16 + (lane >> 2);
        long long r1 = r0 + 8;
        #pragma unroll
        for (int j = 0; j < 4; j++) {
            int cn = n0 + wn + j * 8 + (lane & 3) * 2;
            if (cn >= N) continue;
            float v00 = acc[i][j][0], v01 = acc[i][j][1];
            float v10 = acc[i][j][2], v11 = acc[i][j][3];
            if (bias) {
                float b0 = bias[cn], b1 = bias[cn + 1];
                v00 += b0; v01 += b1; v10 += b0; v11 += b1;
            }
            if (ACT == 1) {
                v00 = fmaxf(v00, 0.f); v01 = fmaxf(v01, 0.f);
                v10 = fmaxf(v10, 0.f); v11 = fmaxf(v11, 0.f);
            }
            if (ACT == 2) {
                v00 = 0.5f * v00 * (1.f + erff(v00 * 0.70710678118654752f));
                v01 = 0.5f * v01 * (1.f + erff(v01 * 0.70710678118654752f));
                v10 = 0.5f * v10 * (1.f + erff(v10 * 0.70710678118654752f));
                v11 = 0.5f * v11 * (1.f + erff(v11 * 0.70710678118654752f));
            }
            if (RES) {
                v00 += Rp[r0 * N + cn]; v01 += Rp[r0 * N + cn + 1];
                v10 += Rp[r1 * N + cn]; v11 += Rp[r1 * N + cn + 1];
            }
            float2 o0 = {v00, v01}, o1 = {v10, v11};
            *(float2*)&C[r0 * N + cn] = o0;
            *(float2*)&C[r1 * N + cn] = o1;
        }
    }
}

// ---------------------------------------------------------------------------
// u-GEMM with fused logits epilogue (scalar frag loads).
// ---------------------------------------------------------------------------
__global__ __launch_bounds__(256, 2)
void ugemm_tc(const float* __restrict__ scores, const float* __restrict__ la,
              const float* __restrict__ ga, float* __restrict__ lpart)
{
    int z = blockIdx.z;                   // bh
    int b = z >> 2;
    const float* A = scores + (long long)z * 512 * 512;
    const float* W = la + (long long)b * 512 * DIM;
    const float* gab = ga + (long long)b * 512 * DIM;

    __shared__ __align__(16) float As[2][128][20];
    __shared__ __align__(16) float Bs[2][16][136];

    int m0 = blockIdx.y * 128, n0 = blockIdx.x * 128;
    int tid = threadIdx.x;
    int warp = tid >> 5, lane = tid & 31;
    int wm = (warp >> 2) * 64;
    int wn = (warp & 3) * 32;

    float acc[4][4][4];
    #pragma unroll
    for (int i = 0; i < 4; i++)
        #pragma unroll
        for (int j = 0; j < 4; j++)
            #pragma unroll
            for (int r = 0; r < 4; r++) acc[i][j][r] = 0.f;

    int arow = tid >> 1, akq = (tid & 1) * 8;
    const float* Ap = A + (long long)(m0 + arow) * 512 + akq;
    int bkr = tid >> 4, bnq = (tid & 15) * 8;
    const float* Wp = W + (long long)bkr * DIM + n0 + bnq;

    float4 av0 = *(const float4*)Ap;
    float4 av1 = *(const float4*)(Ap + 4);
    float4 bv0 = *(const float4*)Wp;
    float4 bv1 = *(const float4*)(Wp + 4);

    const int KT = 512 / 16;
    for (int kt = 0; kt < KT; kt++) {
        int buf = kt & 1;
        As[buf][arow][akq + 0] = to_tf32(av0.x);
        As[buf][arow][akq + 1] = to_tf32(av0.y);
        As[buf][arow][akq + 2] = to_tf32(av0.z);
        As[buf][arow][akq + 3] = to_tf32(av0.w);
        As[buf][arow][akq + 4] = to_tf32(av1.x);
        As[buf][arow][akq + 5] = to_tf32(av1.y);
        As[buf][arow][akq + 6] = to_tf32(av1.z);
        As[buf][arow][akq + 7] = to_tf32(av1.w);
        Bs[buf][bkr][bnq + 0] = to_tf32(bv0.x);
        Bs[buf][bkr][bnq + 1] = to_tf32(bv0.y);
        Bs[buf][bkr][bnq + 2] = to_tf32(bv0.z);
        Bs[buf][bkr][bnq + 3] = to_tf32(bv0.w);
        Bs[buf][bkr][bnq + 4] = to_tf32(bv1.x);
        Bs[buf][bkr][bnq + 5] = to_tf32(bv1.y);
        Bs[buf][bkr][bnq + 6] = to_tf32(bv1.z);
        Bs[buf][bkr][bnq + 7] = to_tf32(bv1.w);

        if (kt + 1 < KT) {
            Ap += 16;
            Wp += (long long)16 * DIM;
            av0 = *(const float4*)Ap;
            av1 = *(const float4*)(Ap + 4);
            bv0 = *(const float4*)Wp;
            bv1 = *(const float4*)(Wp + 4);
        }
        __syncthreads();

        #pragma unroll
        for (int ks = 0; ks < 2; ks++) {
            int ko = ks * 8;
            uint32_t af[4][4], bf[4][2];
            #pragma unroll
            for (int i = 0; i < 4; i++) {
                int mr = wm + i * 16 + (lane >> 2);
                int kc = ko + (lane & 3);
                af[i][0] = __float_as_uint(As[buf][mr][kc]);
                af[i][1] = __float_as_uint(As[buf][mr + 8][kc]);
                af[i][2] = __float_as_uint(As[buf][mr][kc + 4]);
                af[i][3] = __float_as_uint(As[buf][mr + 8][kc + 4]);
            }
            #pragma unroll
            for (int j = 0; j < 4; j++) {
                int nc = wn + j * 8 + (lane >> 2);
                int kr = ko + (lane & 3);
                bf[j][0] = __float_as_uint(Bs[buf][kr][nc]);
                bf[j][1] = __float_as_uint(Bs[buf][kr + 4][nc]);
            }
            #pragma unroll
            for (int i = 0; i < 4; i++)
                #pragma unroll
                for (int j = 0; j < 4; j++)
                    mma_tf32(acc[i][j], af[i], bf[j]);
        }
    }

    // ---- fused logits epilogue ----
    float* gs = (float*)As;   // reuse: [32][132] chunk of ga tile
    float colacc[4][2];
    #pragma unroll
    for (int j = 0; j < 4; j++) { colacc[j][0] = 0.f; colacc[j][1] = 0.f; }

    for (int c = 0; c < 4; c++) {
        __syncthreads();
        #pragma unroll
        for (int it = 0; it < 4; it++) {
            int e = tid + 256 * it;
            int row = e >> 5;
            int c4 = (e & 31) * 4;
            *(float4*)&gs[row * 132 + c4] =
                *(const float4*)&gab[(long long)(m0 + c * 32 + row) * DIM + n0 + c4];
        }
        __syncthreads();
        #pragma unroll
        for (int i = 0; i < 4; i++) {
            if (((wm + i * 16) >> 5) != c) continue;
            int lr0 = wm + i * 16 + (lane >> 2) - c * 32;
            #pragma unroll
            for (int j = 0; j < 4; j++) {
                int cn = wn + j * 8 + (lane & 3) * 2;
                colacc[j][0] += acc[i][j][0] * gs[lr0 * 132 + cn];
                colacc[j][1] += acc[i][j][1] * gs[lr0 * 132 + cn + 1];
                colacc[j][0] += acc[i][j][2] * gs[(lr0 + 8) * 132 + cn];
                colacc[j][1] += acc[i][j][3] * gs[(lr0 + 8) * 132 + cn + 1];
            }
        }
    }

    #pragma unroll
    for (int o = 4; o < 32; o <<= 1)
        #pragma unroll
        for (int j = 0; j < 4; j++) {
            colacc[j][0] += __shfl_down_sync(0xffffffffu, colacc[j][0], o);
            colacc[j][1] += __shfl_down_sync(0xffffffffu, colacc[j][1], o);
        }

    float* red = (float*)Bs;
    __syncthreads();
    if (lane < 4) {
        #pragma unroll
        for (int j = 0; j < 4; j++) {
            red[(warp >> 2) * 128 + wn + j * 8 + lane * 2]     = colacc[j][0];
            red[(warp >> 2) * 128 + wn + j * 8 + lane * 2 + 1] = colacc[j][1];
        }
    }
    __syncthreads();
    if (tid < 128)
        lpart[((long long)z * 4 + blockIdx.y) * 384 + n0 + tid] = red[tid] + red[128 + tid];
}

// ---------------------------------------------------------------------------
// Cross scores via TF32 MMA, double-buffered, scalar frag loads.
// ---------------------------------------------------------------------------
__global__ __launch_bounds__(256, 2)
void cross_tc(const float* __restrict__ qh, const float* __restrict__ kh,
              const float* __restrict__ att_bias, const int* __restrict__ mask,
              float* __restrict__ scores)
{
    int bh = blockIdx.z;
    int b = bh >> 2, h = bh & 3;
    const float* Ab = qh + (long long)b * 512 * DIM + h * DH;
    const float* Bb = kh + (long long)b * 512 * DIM + h * DH;

    __shared__ __align__(16) float As[2][128][20];
    __shared__ __align__(16) float Bs[2][16][136];

    int v0 = blockIdx.y * 128, q0 = blockIdx.x * 128;
    int tid = threadIdx.x;
    int warp = tid >> 5, lane = tid & 31;
    int wm = (warp >> 2) * 64;
    int wn = (warp & 3) * 32;

    float acc[4][4][4];
    #pragma unroll
    for (int i = 0; i < 4; i++)
        #pragma unroll
        for (int j = 0; j < 4; j++)
            #pragma unroll
            for (int r = 0; r < 4; r++) acc[i][j][r] = 0.f;

    int arow = tid >> 1, akq = (tid & 1) * 8;
    const float* Ap = Ab + (long long)(v0 + arow) * DIM + akq;
    const float* Bp = Bb + (long long)(q0 + arow) * DIM + akq;

    float4 av0 = *(const float4*)Ap;
    float4 av1 = *(const float4*)(Ap + 4);
    float4 bv0 = *(const float4*)Bp;
    float4 bv1 = *(const float4*)(Bp + 4);

    const int KT = DH / 16;   // 6
    for (int kt = 0; kt < KT; kt++) {
        int buf = kt & 1;
        As[buf][arow][akq + 0] = to_tf32(av0.x);
        As[buf][arow][akq + 1] = to_tf32(av0.y);
        As[buf][arow][akq + 2] = to_tf32(av0.z);
        As[buf][arow][akq + 3] = to_tf32(av0.w);
        As[buf][arow][akq + 4] = to_tf32(av1.x);
        As[buf][arow][akq + 5] = to_tf32(av1.y);
        As[buf][arow][akq + 6] = to_tf32(av1.z);
        As[buf][arow][akq + 7] = to_tf32(av1.w);
        Bs[buf][akq + 0][arow] = to_tf32(bv0.x);
        Bs[buf][akq + 1][arow] = to_tf32(bv0.y);
        Bs[buf][akq + 2][arow] = to_tf32(bv0.z);
        Bs[buf][akq + 3][arow] = to_tf32(bv0.w);
        Bs[buf][akq + 4][arow] = to_tf32(bv1.x);
        Bs[buf][akq + 5][arow] = to_tf32(bv1.y);
        Bs[buf][akq + 6][arow] = to_tf32(bv1.z);
        Bs[buf][akq + 7][arow] = to_tf32(bv1.w);

        if (kt + 1 < KT) {
            Ap += 16; Bp += 16;
            av0 = *(const float4*)Ap;
            av1 = *(const float4*)(Ap + 4);
            bv0 = *(const float4*)Bp;
            bv1 = *(const float4*)(Bp + 4);
        }
        __syncthreads();

        #pragma unroll
        for (int ks = 0; ks < 2; ks++) {
            int ko = ks * 8;
            uint32_t af[4][4], bf[4][2];
            #pragma unroll
            for (int i = 0; i < 4; i++) {
                int mr = wm + i * 16 + (lane >> 2);
                int kc = ko + (lane & 3);
                af[i][0] = __float_as_uint(As[buf][mr][kc]);
                af[i][1] = __float_as_uint(As[buf][mr + 8][kc]);
                af[i][2] = __float_as_uint(As[buf][mr][kc + 4]);
                af[i][3] = __float_as_uint(As[buf][mr + 8][kc + 4]);
            }
            #pragma unroll
            for (int j = 0; j < 4; j++) {
                int nc = wn + j * 8 + (lane >> 2);
                int kr = ko + (lane & 3);
                bf[j][0] = __float_as_uint(Bs[buf][kr][nc]);
                bf[j][1] = __float_as_uint(Bs[buf][kr + 4][nc]);
            }
            #pragma unroll
            for (int i = 0; i < 4; i++)
                #pragma unroll
                for (int j = 0; j < 4; j++)
                    mma_tf32(acc[i][j], af[i], bf[j]);
        }
    }

    const float scale = 0.10206207261596575f; // 1/sqrt(96)
    float biash = att_bias[h];
    float* out = scores + (long long)bh * 512 * 512;
    #pragma unroll
    for (int i = 0; i < 4; i++) {
        int va = v0 + wm + i * 16 + (lane >> 2);
        int vb = va + 8;
        bool ma = (mask[b * 512 + va] != 0);
        bool mb = (mask[b * 512 + vb] != 0);
        #pragma unroll
        for (int j = 0; j < 4; j++) {
            int cq = q0 + wn + j * 8 + (lane & 3) * 2;
            float2 oa, ob;
            oa.x = ma ? 0.f : (acc[i][j][0] * scale + biash);
            oa.y = ma ? 0.f : (acc[i][j][1] * scale + biash);
            ob.x = mb ? 0.f : (acc[i][j][2] * scale + biash);
            ob.y = mb ? 0.f : (acc[i][j][3] * scale + biash);
            *(float2*)&out[(long long)va * 512 + cq] = oa;
            *(float2*)&out[(long long)vb * 512 + cq] = ob;
        }
    }
}

// ---------------------------------------------------------------------------
// Flash self-attention (fp32): out = softmax(QK^T/sqrt(32)) @ V
// bh spans 2*BATCH*TH = 192 (both streams).
// ---------------------------------------------------------------------------
__global__ __launch_bounds__(256, 2)
void flash_attn_k(const float* __restrict__ qkv, float* __restrict__ out)
{
    int bh = blockIdx.y;
    int b = bh / TH, h = bh % TH;
    int i0 = blockIdx.x * 64;
    const float* base = qkv + (long long)b * 512 * 288;
    const float* qb = base + h * 32;
    const float* kb = base + 96 + h * 32;
    const float* vb = base + 192 + h * 32;

    __shared__ float qs[64][36];
    __shared__ float ks[64][36];
    __shared__ float vs[64][36];
    __shared__ float ps[64][65];

    int tid = threadIdx.x;
    int r = tid >> 2, tq = tid & 3;

    for (int e = tid; e < 512; e += 256) {
        int row = e >> 3, c4 = (e & 7) * 4;
        *(float4*)&qs[row][c4] = *(const float4*)&qb[(long long)(i0 + row) * 288 + c4];
    }
    __syncthreads();
    float q[32];
    #pragma unroll
    for (int i = 0; i < 8; i++) *(float4*)&q[i * 4] = *(const float4*)&qs[r][i * 4];

    float O[8] = {};
    float mrow = -INFINITY, lrow = 0.f;
    const float scale = 0.1767766952966369f;

    for (int j0 = 0; j0 < 512; j0 += 64) {
        __syncthreads();
        for (int e = tid; e < 512; e += 256) {
            int row = e >> 3, c4 = (e & 7) * 4;
            *(float4*)&ks[row][c4] = *(const float4*)&kb[(long long)(j0 + row) * 288 + c4];
            *(float4*)&vs[row][c4] = *(const float4*)&vb[(long long)(j0 + row) * 288 + c4];
        }
        __syncthreads();

        float s[16];
        #pragma unroll
        for (int jj = 0; jj < 16; jj++) {
            int j = jj * 4 + tq;
            float a = 0.f;
            #pragma unroll
            for (int d4 = 0; d4 < 8; d4++) {
                float4 kk = *(const float4*)&ks[j][d4 * 4];
                a += q[d4*4+0]*kk.x + q[d4*4+1]*kk.y + q[d4*4+2]*kk.z + q[d4*4+3]*kk.w;
            }
            s[jj] = a * scale;
        }
        float smax = s[0];
        #pragma unroll
        for (int jj = 1; jj < 16; jj++) smax = fmaxf(smax, s[jj]);
        #pragma unroll
        for (int o = 1; o < 4; o <<= 1)
            smax = fmaxf(smax, __shfl_xor_sync(0xffffffffu, smax, o));
        float mnew = fmaxf(mrow, smax);
        float corr = __expf(mrow - mnew);
        float psum = 0.f;
        #pragma unroll
        for (int jj = 0; jj < 16; jj++) {
            float p = __expf(s[jj] - mnew);
            ps[r][jj * 4 + tq] = p;
            psum += p;
        }
        #pragma unroll
        for (int o = 1; o < 4; o <<= 1)
            psum += __shfl_xor_sync(0xffffffffu, psum, o);
        lrow = lrow * corr + psum;
        mrow = mnew;
        #pragma unroll
        for (int d = 0; d < 8; d++) O[d] *= corr;
        __syncwarp();

        int d0 = tq * 8;
        #pragma unroll 8
        for (int j = 0; j < 64; j++) {
            float pj = ps[r][j];
            float4 v0 = *(const float4*)&vs[j][d0];
            float4 v1 = *(const float4*)&vs[j][d0 + 4];
            O[0] += pj * v0.x; O[1] += pj * v0.y; O[2] += pj * v0.z; O[3] += pj * v0.w;
            O[4] += pj * v1.x; O[5] += pj * v1.y; O[6] += pj * v1.z; O[7] += pj * v1.w;
        }
    }

    float inv = 1.f / lrow;
    float* ob = out + (long long)(b * 512 + i0 + r) * 96 + h * 32 + tq * 8;
    float4 o0 = {O[0]*inv, O[1]*inv, O[2]*inv, O[3]*inv};
    float4 o1 = {O[4]*inv, O[5]*inv, O[6]*inv, O[7]*inv};
    *(float4*)ob = o0;
    *(float4*)(ob + 4) = o1;
}

// ---------------------------------------------------------------------------
// mask / final head
// ---------------------------------------------------------------------------
__global__ void mask_k(const float* __restrict__ gf, int* __restrict__ mask)
{
    int gw = (blockIdx.x * blockDim.x + threadIdx.x) >> 5;
    int lane = threadIdx.x & 31;
    if (gw >= ROWS) return;
    const float* row = gf + (long long)gw * GD;
    float s = 0.f;
    for (int i = lane; i < GD; i += 32) s += fabsf(row[i]);
    #pragma unroll
    for (int o = 16; o > 0; o >>= 1) s += __shfl_down_sync(0xffffffffu, s, o);
    if (lane == 0) mask[gw] = (s == 0.0f) ? 1 : 0;
}

__global__ void final_k(const float* __restrict__ lpart,
                        const float* __restrict__ bn_g, const float* __restrict__ bn_b,
                        const float* __restrict__ bn_mean, const float* __restrict__ bn_var,
                        const float* __restrict__ Wf, const float* __restrict__ bf,
                        float* __restrict__ out)
{
    int b = blockIdx.x, t = threadIdx.x;
    float pooled = 0.f;
    const float* lb = lpart + (long long)b * 16 * 384;
    #pragma unroll
    for (int hv = 0; hv < 16; hv++) {
        const float* lp = lb + hv * 384 + t * 3;
        pooled += lp[0] + lp[1] + lp[2];
    }
    float bn = (pooled - bn_mean[t]) * rsqrtf(bn_var[t] + 1e-5f) * bn_g[t] + bn_b[t];
    __shared__ float sh[128];
    sh[t] = bn * Wf[t];
    __syncthreads();
    for (int s = 64; s > 0; s >>= 1) {
        if (t < s) sh[t] += sh[t + s];
        __syncthreads();
    }
    if (t == 0) out[b] = sh[0] + bf[0];
}

// ---------------------------------------------------------------------------
// Host side
// ---------------------------------------------------------------------------
extern "C" void kernel_launch(void* const* d_in, const int* in_sizes, int n_in,
                              void* d_out, int out_size)
{
    const float* global_feat = (const float*)d_in[0];
    const float* local_feat  = (const float*)d_in[1];
    const float* Wg    = (const float*)d_in[2];
    const float* bg    = (const float*)d_in[3];
    const float* Wl    = (const float*)d_in[4];
    const float* bl    = (const float*)d_in[5];
    const float* ln1_g = (const float*)d_in[6];
    const float* ln1_b = (const float*)d_in[7];
    const float* Wqkv  = (const float*)d_in[8];
    const float* Wo    = (const float*)d_in[9];
    const float* bo    = (const float*)d_in[10];
    const float* ln2_g = (const float*)d_in[11];
    const float* ln2_b = (const float*)d_in[12];
    const float* W1    = (const float*)d_in[13];
    const float* b1    = (const float*)d_in[14];
    const float* W2    = (const float*)d_in[15];
    const float* b2    = (const float*)d_in[16];
    const float* Wq       = (const float*)d_in[17];
    const float* Wk       = (const float*)d_in[18];
    const float* att_bias = (const float*)d_in[19];
    const float* bn_g     = (const float*)d_in[20];
    const float* bn_b     = (const float*)d_in[21];
    const float* bn_mean  = (const float*)d_in[22];
    const float* bn_var   = (const float*)d_in[23];
    const float* Wf       = (const float*)d_in[24];
    const float* bf       = (const float*)d_in[25];

    void *p;
    cudaGetSymbolAddress(&p, g_act);     float* act     = (float*)p;
    cudaGetSymbolAddress(&p, g_qkv);     float* qkv     = (float*)p;
    cudaGetSymbolAddress(&p, g_attnout); float* attnout = (float*)p;
    cudaGetSymbolAddress(&p, g_ff);      float* ff      = (float*)p;
    cudaGetSymbolAddress(&p, g_qh);      float* qh      = (float*)p;
    cudaGetSymbolAddress(&p, g_kh);      float* kh      = (float*)p;
    cudaGetSymbolAddress(&p, g_lpart);   float* lpart   = (float*)p;
    cudaGetSymbolAddress(&p, g_lnstat);  float* lnstat  = (float*)p;
    cudaGetSymbolAddress(&p, g_mask);    int*   mask    = (int*)p;

    float* ga = act;                          // stream 0
    float* la = act + (long long)ROWS * DIM;  // stream 1

    float* out_scalar = (float*)d_out;
    float* scores = out_scalar + BATCH;

    const long long SACT = (long long)ROWS * DIM;
    const long long SQKV = (long long)ROWS * 288;
    const long long SAO  = (long long)ROWS * 96;
    const long long SFF  = (long long)ROWS * 128;
    const long long SLN  = (long long)ROWS * 2;

    // 1) Input projections (ReLU) — different K/W, separate launches
    gemm_tc<1, false, false><<<dim3(3, 128, 1), 256>>>(global_feat, Wg, bg, nullptr, ga,
                                                       nullptr, nullptr, nullptr,
                                                       ROWS, DIM, GD, 0, 0, 0, 0, 1);
    gemm_tc<1, false, false><<<dim3(3, 128, 1), 256>>>(local_feat, Wl, bl, nullptr, la,
                                                       nullptr, nullptr, nullptr,
                                                       ROWS, DIM, LD, 0, 0, 0, 0, 1);

    // 2) Transformer, both streams batched via z=2 (shared weights: sW=0)
    lnstats_k<<<2 * ROWS / 8, 256>>>(act, lnstat);
    gemm_tc<0, false, true><<<dim3(3, 128, 2), 256>>>(act, Wqkv, nullptr, nullptr, qkv,
                                                      lnstat, ln1_g, ln1_b,
                                                      ROWS, 288, 384, SACT, 0, SQKV, SLN, 1);
    flash_attn_k<<<dim3(8, 192), 256>>>(qkv, attnout);
    gemm_tc<0, true, false><<<dim3(3, 128, 2), 256>>>(attnout, Wo, bo, act, act,
                                                      nullptr, nullptr, nullptr,
                                                      ROWS, 384, 96, SAO, 0, SACT, 0, 1);
    lnstats_k<<<2 * ROWS / 8, 256>>>(act, lnstat);
    gemm_tc<2, false, true><<<dim3(1, 128, 2), 256>>>(act, W1, b1, nullptr, ff,
                                                      lnstat, ln2_g, ln2_b,
                                                      ROWS, 128, 384, SACT, 0, SFF, SLN, 1);
    gemm_tc<0, true, false><<<dim3(3, 128, 2), 256>>>(ff, W2, b2, act, act,
                                                      nullptr, nullptr, nullptr,
                                                      ROWS, 384, 128, SFF, 0, SACT, 0, 1);

    // 3) Cross q/k projections
    gemm_tc<0, false, false><<<dim3(3, 128, 1), 256>>>(ga, Wq, nullptr, nullptr, qh,
                                                       nullptr, nullptr, nullptr,
                                                       ROWS, DIM, DIM, 0, 0, 0, 0, 1);
    gemm_tc<0, false, false><<<dim3(3, 128, 1), 256>>>(la, Wk, nullptr, nullptr, kh,
                                                       nullptr, nullptr, nullptr,
                                                       ROWS, DIM, DIM, 0, 0, 0, 0, 1);

    // 4) Mask + cross scores (into d_out)
    mask_k<<<(ROWS * 32 + 255) / 256, 256>>>(global_feat, mask);
    cross_tc<<<dim3(4, 4, 128), 256>>>(qh, kh, att_bias, mask, scores);

    // 5) u-GEMM with fused logits reduction
    ugemm_tc<<<dim3(3, 4, 128), 256>>>(scores, la, ga, lpart);

    // 6) head
    final_k<<<BATCH, 128>>>(lpart, bn_g, bn_b, bn_mean, bn_var, Wf, bf, out_scalar);
}